// round 2
// baseline (speedup 1.0000x reference)
#include <cuda_runtime.h>
#include <cuda_bf16.h>
#include <math.h>

#define N_NODES_MAX 100000
#define HID 32
#define IN_DIM 4
#define N_GRAPHS_MAX 64
#define EPSV 1e-5f

// ---------------- scratch (static device memory; no allocs allowed) ----------------
__device__ float g_agg[N_NODES_MAX * HID];      // segment-max accumulator (12.8 MB)
__device__ float g_stats[2 * HID];              // [0:32) sum, [32:64) sumsq
__device__ float g_scale[HID];
__device__ float g_shift[HID];
__device__ float g_gsum[N_GRAPHS_MAX * HID];
__device__ int   g_gcnt[N_GRAPHS_MAX];

// ---------------- helpers ----------------
// float atomic max via sign-split int/uint ordering. Valid when buffer is
// initialized to -inf (0xFF800000).
__device__ __forceinline__ void atomicMaxFloat(float* addr, float v) {
    int vi = __float_as_int(v);
    if (vi >= 0) {
        atomicMax((int*)addr, vi);
    } else {
        atomicMin((unsigned int*)addr, (unsigned int)vi);
    }
}

// ---------------- kernel 1: init scratch ----------------
__global__ void init_kernel(int n_nodes, int n_graphs) {
    int i = blockIdx.x * blockDim.x + threadIdx.x;
    int total = n_nodes * HID;
    if (i < total) g_agg[i] = __int_as_float(0xFF800000);  // -inf
    if (i < 2 * HID) g_stats[i] = 0.f;
    if (i < n_graphs * HID) g_gsum[i] = 0.f;
    if (i < n_graphs) g_gcnt[i] = 0;
}

// ---------------- kernel 2: fused edge MLP + segment-max atomics ----------------
__global__ void __launch_bounds__(256) edge_kernel(
    const float* __restrict__ x,
    const int* __restrict__ ei,   // [2, E] row-major: row 0 = src, row 1 = dst (int32)
    const float* __restrict__ W1,       // [8, 32]
    const float* __restrict__ b1,       // [32]
    const float* __restrict__ W2,       // [32, 32]
    const float* __restrict__ b2,       // [32]
    int E)
{
    __shared__ float sW1[2 * IN_DIM * HID];   // 256
    __shared__ float sW2[HID * HID];          // 1024
    __shared__ float sb1[HID];
    __shared__ float sb2[HID];

    for (int i = threadIdx.x; i < 2 * IN_DIM * HID; i += blockDim.x) sW1[i] = W1[i];
    for (int i = threadIdx.x; i < HID * HID; i += blockDim.x)        sW2[i] = W2[i];
    if (threadIdx.x < HID) { sb1[threadIdx.x] = b1[threadIdx.x]; sb2[threadIdx.x] = b2[threadIdx.x]; }
    __syncthreads();

    int stride = gridDim.x * blockDim.x;
    for (int e = blockIdx.x * blockDim.x + threadIdx.x; e < E; e += stride) {
        int s = ei[e];
        int d = ei[E + e];

        const float4 xi = *reinterpret_cast<const float4*>(x + (size_t)d * IN_DIM);
        const float4 xj = *reinterpret_cast<const float4*>(x + (size_t)s * IN_DIM);

        float msg[8];
        msg[0] = xi.x; msg[1] = xi.y; msg[2] = xi.z; msg[3] = xi.w;
        msg[4] = xj.x - xi.x; msg[5] = xj.y - xi.y; msg[6] = xj.z - xi.z; msg[7] = xj.w - xi.w;

        // layer 1: hid[c] = relu(b1[c] + sum_k msg[k]*W1[k][c])
        float hid[HID];
        #pragma unroll
        for (int cc = 0; cc < HID / 4; cc++) {
            float4 acc = reinterpret_cast<const float4*>(sb1)[cc];
            #pragma unroll
            for (int k = 0; k < 8; k++) {
                float4 wv = reinterpret_cast<const float4*>(sW1 + k * HID)[cc];
                acc.x += msg[k] * wv.x;
                acc.y += msg[k] * wv.y;
                acc.z += msg[k] * wv.z;
                acc.w += msg[k] * wv.w;
            }
            hid[4 * cc + 0] = fmaxf(acc.x, 0.f);
            hid[4 * cc + 1] = fmaxf(acc.y, 0.f);
            hid[4 * cc + 2] = fmaxf(acc.z, 0.f);
            hid[4 * cc + 3] = fmaxf(acc.w, 0.f);
        }

        // layer 2: out[c] = b2[c] + sum_j hid[j]*W2[j][c]
        float out[HID];
        #pragma unroll
        for (int cc = 0; cc < HID / 4; cc++) {
            float4 bv = reinterpret_cast<const float4*>(sb2)[cc];
            out[4 * cc + 0] = bv.x; out[4 * cc + 1] = bv.y;
            out[4 * cc + 2] = bv.z; out[4 * cc + 3] = bv.w;
        }
        #pragma unroll
        for (int j = 0; j < HID; j++) {
            float hj = hid[j];
            const float4* wrow = reinterpret_cast<const float4*>(sW2 + j * HID);
            #pragma unroll
            for (int cc = 0; cc < HID / 4; cc++) {
                float4 wv = wrow[cc];
                out[4 * cc + 0] += hj * wv.x;
                out[4 * cc + 1] += hj * wv.y;
                out[4 * cc + 2] += hj * wv.z;
                out[4 * cc + 3] += hj * wv.w;
            }
        }

        float* base = g_agg + (size_t)d * HID;
        #pragma unroll
        for (int c = 0; c < HID; c++) atomicMaxFloat(base + c, out[c]);
    }
}

// ---------------- kernel 3: -inf -> 0 fixup + per-channel sum / sumsq ----------------
__global__ void __launch_bounds__(256) stats_kernel(int n_nodes) {
    int t = threadIdx.x;
    float sum = 0.f, sq = 0.f;
    int total = n_nodes * HID;
    for (int i = blockIdx.x * blockDim.x + t; i < total; i += gridDim.x * blockDim.x) {
        float v = g_agg[i];
        if (!isfinite(v)) { v = 0.f; g_agg[i] = 0.f; }
        sum += v;
        sq += v * v;
    }
    // channel of this thread is constant mod 32: stride is a multiple of 32
    __shared__ float sS[256];
    __shared__ float sQ[256];
    sS[t] = sum; sQ[t] = sq;
    __syncthreads();
    #pragma unroll
    for (int s = 128; s >= 32; s >>= 1) {
        if (t < s) { sS[t] += sS[t + s]; sQ[t] += sQ[t + s]; }
        __syncthreads();
    }
    if (t < 32) {
        atomicAdd(&g_stats[t], sS[t]);
        atomicAdd(&g_stats[32 + t], sQ[t]);
    }
}

// ---------------- kernel 4: fold batchnorm into scale/shift ----------------
__global__ void bn_kernel(const float* __restrict__ gamma, const float* __restrict__ beta,
                          int n_nodes) {
    int c = threadIdx.x;
    if (c >= HID) return;
    float inv_n = 1.f / (float)n_nodes;
    float mean = g_stats[c] * inv_n;
    float var = g_stats[32 + c] * inv_n - mean * mean;
    float sc = gamma[c] * rsqrtf(var + EPSV);
    g_scale[c] = sc;
    g_shift[c] = beta[c] - mean * sc;
}

// ---------------- kernel 5: normalize + relu + per-graph mean-pool ----------------
// batch is sorted, so each thread accumulates in registers and flushes on
// graph-id change -> tiny number of global atomics.
__global__ void __launch_bounds__(256) pool_kernel(const int* __restrict__ batch,
                                                   int n_nodes) {
    int c = threadIdx.x & 31;
    int w = threadIdx.x >> 5;  // 0..7
    float sc = g_scale[c];
    float sh = g_shift[c];

    int chunk = (n_nodes + gridDim.x - 1) / gridDim.x;
    int n0 = blockIdx.x * chunk;
    int n1 = min(n0 + chunk, n_nodes);

    float acc = 0.f;
    int cur = -1;
    int cnt = 0;
    for (int n = n0 + w; n < n1; n += 8) {
        int g = batch[n];
        float v = g_agg[(size_t)n * HID + c];
        v = fmaxf(v * sc + sh, 0.f);
        if (g != cur) {
            if (cur >= 0) {
                atomicAdd(&g_gsum[cur * HID + c], acc);
                if (c == 0) atomicAdd(&g_gcnt[cur], cnt);
            }
            cur = g; acc = 0.f; cnt = 0;
        }
        acc += v; cnt++;
    }
    if (cur >= 0) {
        atomicAdd(&g_gsum[cur * HID + c], acc);
        if (c == 0) atomicAdd(&g_gcnt[cur], cnt);
    }
}

// ---------------- kernel 6: per-graph readout MLP 32->16->1 ----------------
__global__ void final_kernel(const float* __restrict__ Wr1, const float* __restrict__ br1,
                             const float* __restrict__ Wr2, const float* __restrict__ br2,
                             float* __restrict__ out, int n_graphs) {
    int g = threadIdx.x + blockIdx.x * blockDim.x;
    if (g >= n_graphs) return;
    float inv_cnt = 1.f / fmaxf((float)g_gcnt[g], 1.f);
    float p[HID];
    #pragma unroll
    for (int c = 0; c < HID; c++) p[c] = g_gsum[g * HID + c] * inv_cnt;
    float h[16];
    #pragma unroll
    for (int m = 0; m < 16; m++) {
        float a = br1[m];
        #pragma unroll
        for (int c = 0; c < HID; c++) a += p[c] * Wr1[c * 16 + m];
        h[m] = fmaxf(a, 0.f);
    }
    float o = br2[0];
    #pragma unroll
    for (int m = 0; m < 16; m++) o += h[m] * Wr2[m];
    out[g] = o;
}

// ---------------- launch ----------------
extern "C" void kernel_launch(void* const* d_in, const int* in_sizes, int n_in,
                              void* d_out, int out_size) {
    const float* x     = (const float*)d_in[0];
    const int*   ei    = (const int*)d_in[1];
    const int*   batch = (const int*)d_in[2];
    const float* W1    = (const float*)d_in[3];
    const float* b1    = (const float*)d_in[4];
    const float* W2    = (const float*)d_in[5];
    const float* b2    = (const float*)d_in[6];
    const float* gamma = (const float*)d_in[7];
    const float* beta  = (const float*)d_in[8];
    const float* Wr1   = (const float*)d_in[9];
    const float* br1   = (const float*)d_in[10];
    const float* Wr2   = (const float*)d_in[11];
    const float* br2   = (const float*)d_in[12];
    float* out = (float*)d_out;

    int E = in_sizes[1] / 2;
    int n_nodes = in_sizes[2];
    int n_graphs = out_size;

    int total = n_nodes * HID;
    init_kernel<<<(total + 255) / 256, 256>>>(n_nodes, n_graphs);
    edge_kernel<<<1184, 256>>>(x, ei, W1, b1, W2, b2, E);
    stats_kernel<<<592, 256>>>(n_nodes);
    bn_kernel<<<1, 32>>>(gamma, beta, n_nodes);
    pool_kernel<<<256, 256>>>(batch, n_nodes);
    final_kernel<<<1, 64>>>(Wr1, br1, Wr2, br2, out, n_graphs);
}

// round 3
// speedup vs baseline: 8.3347x; 8.3347x over previous
#include <cuda_runtime.h>
#include <cuda_bf16.h>
#include <math.h>

#define N_NODES_MAX 100000
#define E_MAX       1600000
#define HID 32
#define IN_DIM 4
#define N_GRAPHS_MAX 64
#define EPSV 1e-5f

#define SCAN_BS 256
#define SCAN_BLOCKS ((N_NODES_MAX + SCAN_BS - 1) / SCAN_BS)   // 391
#define NPAD (SCAN_BLOCKS * SCAN_BS)                          // 100096

// ---------------- static device scratch ----------------
__device__ float g_agg[N_NODES_MAX * HID];      // per-node aggregated features
__device__ float g_stats[2 * HID];              // [0:32) sum, [32:64) sumsq
__device__ float g_scale[HID];
__device__ float g_shift[HID];
__device__ float g_gsum[N_GRAPHS_MAX * HID];
__device__ int   g_gcnt[N_GRAPHS_MAX];

__device__ int g_cnt[NPAD];                     // histogram of dst
__device__ int g_excl[NPAD];                    // per-block exclusive scan
__device__ int g_bsum[SCAN_BLOCKS];
__device__ int g_bscan[SCAN_BLOCKS];
__device__ int g_offs[N_NODES_MAX + 1];         // CSR offsets
__device__ int g_cursor[NPAD];                  // scatter cursors
__device__ int g_srcsorted[E_MAX];              // src ids sorted by dst

// ---------------- kernel 1: zero scratch ----------------
__global__ void zero_kernel(int n_graphs) {
    int i = blockIdx.x * blockDim.x + threadIdx.x;
    if (i < NPAD) g_cnt[i] = 0;
    if (i < 2 * HID) g_stats[i] = 0.f;
    if (i < n_graphs * HID) g_gsum[i] = 0.f;
    if (i < n_graphs) g_gcnt[i] = 0;
}

// ---------------- kernel 2: histogram of dst ----------------
__global__ void hist_kernel(const int* __restrict__ ei, int E) {
    int e = blockIdx.x * blockDim.x + threadIdx.x;
    if (e < E) atomicAdd(&g_cnt[ei[E + e]], 1);
}

// ---------------- kernels 3-5: exclusive scan of g_cnt -> g_offs ----------------
__global__ void scan_part_kernel(int n) {
    __shared__ int s[SCAN_BS];
    int t = threadIdx.x;
    int i = blockIdx.x * SCAN_BS + t;
    int v = (i < n) ? g_cnt[i] : 0;
    s[t] = v;
    __syncthreads();
    #pragma unroll
    for (int off = 1; off < SCAN_BS; off <<= 1) {
        int tv = (t >= off) ? s[t - off] : 0;
        __syncthreads();
        s[t] += tv;
        __syncthreads();
    }
    g_excl[i] = s[t] - v;                 // exclusive within block
    if (t == SCAN_BS - 1) g_bsum[blockIdx.x] = s[t];
}

__global__ void scan_top_kernel() {
    __shared__ int s[512];
    int t = threadIdx.x;
    int v = (t < SCAN_BLOCKS) ? g_bsum[t] : 0;
    s[t] = v;
    __syncthreads();
    #pragma unroll
    for (int off = 1; off < 512; off <<= 1) {
        int tv = (t >= off) ? s[t - off] : 0;
        __syncthreads();
        s[t] += tv;
        __syncthreads();
    }
    if (t < SCAN_BLOCKS) g_bscan[t] = s[t] - v;
}

__global__ void scan_add_kernel(int n, int E) {
    int i = blockIdx.x * blockDim.x + threadIdx.x;
    if (i < n) {
        int o = g_excl[i] + g_bscan[blockIdx.x * blockDim.x / SCAN_BS + (threadIdx.x / SCAN_BS)];
        // blockDim == SCAN_BS so the above reduces to g_bscan[blockIdx.x]
        g_offs[i] = o;
        g_cursor[i] = o;
    }
    if (i == 0) g_offs[n] = E;
}

// ---------------- kernel 6: scatter src ids into dst-sorted order ----------------
__global__ void scatter_kernel(const int* __restrict__ ei, int E) {
    int e = blockIdx.x * blockDim.x + threadIdx.x;
    if (e < E) {
        int d = ei[E + e];
        int pos = atomicAdd(&g_cursor[d], 1);
        g_srcsorted[pos] = ei[e];
    }
}

// ---------------- kernel 7: warp-per-node fused edge MLP + max + BN stats ----------------
__global__ void __launch_bounds__(256) node_kernel(
    const float* __restrict__ x,
    const float* __restrict__ W1, const float* __restrict__ b1,
    const float* __restrict__ W2, const float* __restrict__ b2,
    int n_nodes)
{
    const int c = threadIdx.x & 31;       // channel = lane
    const int w = threadIdx.x >> 5;       // warp in block (0..7)

    // per-lane weight columns
    float w1r[8];
    #pragma unroll
    for (int k = 0; k < 8; k++) w1r[k] = W1[k * HID + c];
    float w2r[HID];
    #pragma unroll
    for (int j = 0; j < HID; j++) w2r[j] = W2[j * HID + c];
    const float b1c = b1[c];
    const float b2c = b2[c];

    float ssum = 0.f, ssq = 0.f;

    for (int n = blockIdx.x * 8 + w; n < n_nodes; n += gridDim.x * 8) {
        const float4 xi = *reinterpret_cast<const float4*>(x + (size_t)n * IN_DIM);
        const int st = g_offs[n];
        const int en = g_offs[n + 1];

        float acc = -INFINITY;
        for (int e = st; e < en; e++) {
            int s = g_srcsorted[e];                         // broadcast load
            const float4 xj = *reinterpret_cast<const float4*>(x + (size_t)s * IN_DIM);
            float m0 = xi.x, m1 = xi.y, m2 = xi.z, m3 = xi.w;
            float m4 = xj.x - xi.x, m5 = xj.y - xi.y, m6 = xj.z - xi.z, m7 = xj.w - xi.w;

            float h = b1c;
            h = fmaf(m0, w1r[0], h); h = fmaf(m1, w1r[1], h);
            h = fmaf(m2, w1r[2], h); h = fmaf(m3, w1r[3], h);
            h = fmaf(m4, w1r[4], h); h = fmaf(m5, w1r[5], h);
            h = fmaf(m6, w1r[6], h); h = fmaf(m7, w1r[7], h);
            h = fmaxf(h, 0.f);

            float o = b2c;
            #pragma unroll
            for (int j = 0; j < HID; j++)
                o = fmaf(__shfl_sync(0xffffffffu, h, j), w2r[j], o);

            acc = fmaxf(acc, o);
        }
        if (st == en) acc = 0.f;

        g_agg[(size_t)n * HID + c] = acc;                   // coalesced 128B per warp
        ssum += acc;
        ssq += acc * acc;
    }

    // block-level stats flush
    __shared__ float sS[HID], sQ[HID];
    if (threadIdx.x < HID) { sS[threadIdx.x] = 0.f; sQ[threadIdx.x] = 0.f; }
    __syncthreads();
    atomicAdd(&sS[c], ssum);
    atomicAdd(&sQ[c], ssq);
    __syncthreads();
    if (threadIdx.x < HID) {
        atomicAdd(&g_stats[threadIdx.x], sS[threadIdx.x]);
        atomicAdd(&g_stats[HID + threadIdx.x], sQ[threadIdx.x]);
    }
}

// ---------------- kernel 8: fold batchnorm into scale/shift ----------------
__global__ void bn_kernel(const float* __restrict__ gamma, const float* __restrict__ beta,
                          int n_nodes) {
    int c = threadIdx.x;
    if (c >= HID) return;
    float inv_n = 1.f / (float)n_nodes;
    float mean = g_stats[c] * inv_n;
    float var = g_stats[HID + c] * inv_n - mean * mean;
    float sc = gamma[c] * rsqrtf(var + EPSV);
    g_scale[c] = sc;
    g_shift[c] = beta[c] - mean * sc;
}

// ---------------- kernel 9: normalize + relu + per-graph mean pool ----------------
__global__ void __launch_bounds__(256) pool_kernel(const int* __restrict__ batch,
                                                   int n_nodes) {
    int c = threadIdx.x & 31;
    int w = threadIdx.x >> 5;
    float sc = g_scale[c];
    float sh = g_shift[c];

    int chunk = (n_nodes + gridDim.x - 1) / gridDim.x;
    int n0 = blockIdx.x * chunk;
    int n1 = min(n0 + chunk, n_nodes);

    float acc = 0.f;
    int cur = -1;
    int cnt = 0;
    for (int n = n0 + w; n < n1; n += 8) {
        int g = batch[n];
        float v = g_agg[(size_t)n * HID + c];
        v = fmaxf(v * sc + sh, 0.f);
        if (g != cur) {
            if (cur >= 0) {
                atomicAdd(&g_gsum[cur * HID + c], acc);
                if (c == 0) atomicAdd(&g_gcnt[cur], cnt);
            }
            cur = g; acc = 0.f; cnt = 0;
        }
        acc += v; cnt++;
    }
    if (cur >= 0) {
        atomicAdd(&g_gsum[cur * HID + c], acc);
        if (c == 0) atomicAdd(&g_gcnt[cur], cnt);
    }
}

// ---------------- kernel 10: per-graph readout MLP 32->16->1 ----------------
__global__ void final_kernel(const float* __restrict__ Wr1, const float* __restrict__ br1,
                             const float* __restrict__ Wr2, const float* __restrict__ br2,
                             float* __restrict__ out, int n_graphs) {
    int g = threadIdx.x + blockIdx.x * blockDim.x;
    if (g >= n_graphs) return;
    float inv_cnt = 1.f / fmaxf((float)g_gcnt[g], 1.f);
    float p[HID];
    #pragma unroll
    for (int c = 0; c < HID; c++) p[c] = g_gsum[g * HID + c] * inv_cnt;
    float h[16];
    #pragma unroll
    for (int m = 0; m < 16; m++) {
        float a = br1[m];
        #pragma unroll
        for (int c = 0; c < HID; c++) a += p[c] * Wr1[c * 16 + m];
        h[m] = fmaxf(a, 0.f);
    }
    float o = br2[0];
    #pragma unroll
    for (int m = 0; m < 16; m++) o += h[m] * Wr2[m];
    out[g] = o;
}

// ---------------- launch ----------------
extern "C" void kernel_launch(void* const* d_in, const int* in_sizes, int n_in,
                              void* d_out, int out_size) {
    const float* x     = (const float*)d_in[0];
    const int*   ei    = (const int*)d_in[1];
    const int*   batch = (const int*)d_in[2];
    const float* W1    = (const float*)d_in[3];
    const float* b1    = (const float*)d_in[4];
    const float* W2    = (const float*)d_in[5];
    const float* b2    = (const float*)d_in[6];
    const float* gamma = (const float*)d_in[7];
    const float* beta  = (const float*)d_in[8];
    const float* Wr1   = (const float*)d_in[9];
    const float* br1   = (const float*)d_in[10];
    const float* Wr2   = (const float*)d_in[11];
    const float* br2   = (const float*)d_in[12];
    float* out = (float*)d_out;

    int E        = in_sizes[1] / 2;
    int n_nodes  = in_sizes[2];
    int n_graphs = out_size;

    zero_kernel<<<(NPAD + 255) / 256, 256>>>(n_graphs);
    hist_kernel<<<(E + 255) / 256, 256>>>(ei, E);
    scan_part_kernel<<<SCAN_BLOCKS, SCAN_BS>>>(n_nodes);
    scan_top_kernel<<<1, 512>>>();
    scan_add_kernel<<<SCAN_BLOCKS, SCAN_BS>>>(n_nodes, E);
    scatter_kernel<<<(E + 255) / 256, 256>>>(ei, E);
    node_kernel<<<1568, 256>>>(x, W1, b1, W2, b2, n_nodes);
    bn_kernel<<<1, 32>>>(gamma, beta, n_nodes);
    pool_kernel<<<256, 256>>>(batch, n_nodes);
    final_kernel<<<1, 64>>>(Wr1, br1, Wr2, br2, out, n_graphs);
}

// round 4
// speedup vs baseline: 10.7642x; 1.2915x over previous
#include <cuda_runtime.h>
#include <cuda_bf16.h>
#include <math.h>

#define N_NODES_MAX 100000
#define E_MAX       1600000
#define HID 32
#define IN_DIM 4
#define N_GRAPHS_MAX 64
#define EPSV 1e-5f

#define SCAN_BS 256
#define SCAN_BLOCKS ((N_NODES_MAX + SCAN_BS - 1) / SCAN_BS)   // 391
#define NPAD (SCAN_BLOCKS * SCAN_BS)                          // 100096
#define EB 256                                                // edges per block
#define MAX_EBLOCKS ((E_MAX + EB - 1) / EB + 1)

typedef unsigned long long ull;

// ---------------- static device scratch ----------------
__device__ float g_agg[N_NODES_MAX * HID];      // per-node aggregated features (-inf init)
__device__ float g_stats[2 * HID];
__device__ float g_scale[HID];
__device__ float g_shift[HID];
__device__ float g_gsum[N_GRAPHS_MAX * HID];
__device__ int   g_gcnt[N_GRAPHS_MAX];

__device__ int g_cnt[NPAD];
__device__ int g_excl[NPAD];
__device__ int g_bsum[SCAN_BLOCKS];
__device__ int g_bscan[SCAN_BLOCKS];
__device__ int g_offs[N_NODES_MAX + 1];
__device__ int g_cursor[NPAD];
__device__ int g_srcsorted[E_MAX];
__device__ int g_dstsorted[E_MAX];
__device__ int g_bstart[MAX_EBLOCKS];

// ---------------- helpers ----------------
__device__ __forceinline__ void atomicMaxFloat(float* addr, float v) {
    int vi = __float_as_int(v);
    if (vi >= 0) atomicMax((int*)addr, vi);
    else         atomicMin((unsigned int*)addr, (unsigned int)vi);
}

__device__ __forceinline__ ull fma2(ull a, ull b, ull c) {
    ull d;
    asm("fma.rn.f32x2 %0, %1, %2, %3;" : "=l"(d) : "l"(a), "l"(b), "l"(c));
    return d;
}
__device__ __forceinline__ ull dup2(float v) {
    ull d;
    asm("mov.b64 %0, {%1, %1};" : "=l"(d) : "f"(v));
    return d;
}
__device__ __forceinline__ void unpack2(ull p, float& lo, float& hi) {
    asm("mov.b64 {%0, %1}, %2;" : "=f"(lo), "=f"(hi) : "l"(p));
}

// ---------------- kernel 1: init ----------------
__global__ void init_kernel(int n_nodes, int n_graphs) {
    int i = blockIdx.x * blockDim.x + threadIdx.x;
    if (i < n_nodes * HID) g_agg[i] = __int_as_float(0xFF800000);  // -inf
    if (i < NPAD) g_cnt[i] = 0;
    if (i < 2 * HID) g_stats[i] = 0.f;
    if (i < n_graphs * HID) g_gsum[i] = 0.f;
    if (i < n_graphs) g_gcnt[i] = 0;
}

// ---------------- kernel 2: histogram of dst ----------------
__global__ void hist_kernel(const int* __restrict__ ei, int E) {
    int e = blockIdx.x * blockDim.x + threadIdx.x;
    if (e < E) atomicAdd(&g_cnt[ei[E + e]], 1);
}

// ---------------- kernels 3-5: exclusive scan ----------------
__global__ void scan_part_kernel(int n) {
    __shared__ int s[SCAN_BS];
    int t = threadIdx.x;
    int i = blockIdx.x * SCAN_BS + t;
    int v = (i < n) ? g_cnt[i] : 0;
    s[t] = v;
    __syncthreads();
    #pragma unroll
    for (int off = 1; off < SCAN_BS; off <<= 1) {
        int tv = (t >= off) ? s[t - off] : 0;
        __syncthreads();
        s[t] += tv;
        __syncthreads();
    }
    g_excl[i] = s[t] - v;
    if (t == SCAN_BS - 1) g_bsum[blockIdx.x] = s[t];
}

__global__ void scan_top_kernel() {
    __shared__ int s[512];
    int t = threadIdx.x;
    int v = (t < SCAN_BLOCKS) ? g_bsum[t] : 0;
    s[t] = v;
    __syncthreads();
    #pragma unroll
    for (int off = 1; off < 512; off <<= 1) {
        int tv = (t >= off) ? s[t - off] : 0;
        __syncthreads();
        s[t] += tv;
        __syncthreads();
    }
    if (t < SCAN_BLOCKS) g_bscan[t] = s[t] - v;
}

__global__ void scan_add_kernel(int n, int E) {
    int i = blockIdx.x * blockDim.x + threadIdx.x;
    if (i < n) {
        int o = g_excl[i] + g_bscan[blockIdx.x];
        g_offs[i] = o;
        g_cursor[i] = o;
    }
    if (i == 0) g_offs[n] = E;
}

// ---------------- kernel 6: scatter (src,dst) into dst-sorted order ----------------
__global__ void scatter_kernel(const int* __restrict__ ei, int E) {
    int e = blockIdx.x * blockDim.x + threadIdx.x;
    if (e < E) {
        int d = ei[E + e];
        int pos = atomicAdd(&g_cursor[d], 1);
        g_srcsorted[pos] = ei[e];
        g_dstsorted[pos] = d;
    }
}

// ---------------- kernel 7: per-block first node via binary search ----------------
__global__ void bstart_kernel(int nblocks, int n_nodes) {
    int b = blockIdx.x * blockDim.x + threadIdx.x;
    if (b >= nblocks) return;
    int target = b * EB;
    int lo = 0, hi = n_nodes;   // max n in [0,n_nodes] with offs[n] <= target
    while (lo < hi) {
        int mid = (lo + hi + 1) >> 1;
        lo = (g_offs[mid] <= target) ? mid : lo;
        hi = (g_offs[mid] <= target) ? hi : mid - 1;
    }
    g_bstart[b] = lo;
}

// ---------------- kernel 8: edge MLP (packed f32x2) + in-smem segmented max ----------------
__global__ void __launch_bounds__(EB) edge2_kernel(
    const float* __restrict__ x,
    const float* __restrict__ W1, const float* __restrict__ b1,
    const float* __restrict__ W2, const float* __restrict__ b2,
    int E, int n_nodes)
{
    __shared__ __align__(16) float sW1[2 * IN_DIM * HID];
    __shared__ __align__(16) float sW2[HID * HID];
    __shared__ __align__(16) float sb1[HID];
    __shared__ __align__(16) float sb2[HID];
    __shared__ float sOut[EB][HID + 1];

    const int tid = threadIdx.x;
    for (int i = tid; i < 2 * IN_DIM * HID; i += EB) sW1[i] = W1[i];
    for (int i = tid; i < HID * HID; i += EB)        sW2[i] = W2[i];
    if (tid < HID) { sb1[tid] = b1[tid]; sb2[tid] = b2[tid]; }
    __syncthreads();

    const int e0 = blockIdx.x * EB;
    const int e1 = min(e0 + EB, E);
    const int e  = e0 + tid;

    if (e < E) {
        const int s = g_srcsorted[e];
        const int d = g_dstsorted[e];
        const float4 xi = __ldg(reinterpret_cast<const float4*>(x + (size_t)d * IN_DIM));
        const float4 xj = __ldg(reinterpret_cast<const float4*>(x + (size_t)s * IN_DIM));

        float msg[8];
        msg[0] = xi.x; msg[1] = xi.y; msg[2] = xi.z; msg[3] = xi.w;
        msg[4] = xj.x - xi.x; msg[5] = xj.y - xi.y; msg[6] = xj.z - xi.z; msg[7] = xj.w - xi.w;

        const ull* b1p = reinterpret_cast<const ull*>(sb1);
        const ull* b2p = reinterpret_cast<const ull*>(sb2);

        // layer 1: 16 packed accumulators over 32 channels
        ull hp[16];
        #pragma unroll
        for (int cc = 0; cc < 16; cc++) hp[cc] = b1p[cc];
        #pragma unroll
        for (int k = 0; k < 8; k++) {
            ull md = dup2(msg[k]);
            const ull* w1p = reinterpret_cast<const ull*>(sW1 + k * HID);
            #pragma unroll
            for (int cc = 0; cc < 16; cc++) hp[cc] = fma2(md, w1p[cc], hp[cc]);
        }
        float h[32];
        #pragma unroll
        for (int cc = 0; cc < 16; cc++) {
            float lo, hi;
            unpack2(hp[cc], lo, hi);
            h[2 * cc]     = fmaxf(lo, 0.f);
            h[2 * cc + 1] = fmaxf(hi, 0.f);
        }

        // layer 2
        ull op[16];
        #pragma unroll
        for (int cc = 0; cc < 16; cc++) op[cc] = b2p[cc];
        #pragma unroll
        for (int j = 0; j < HID; j++) {
            ull hd = dup2(h[j]);
            const ull* w2p = reinterpret_cast<const ull*>(sW2 + j * HID);
            #pragma unroll
            for (int cc = 0; cc < 16; cc++) op[cc] = fma2(hd, w2p[cc], op[cc]);
        }

        #pragma unroll
        for (int cc = 0; cc < 16; cc++) {
            float lo, hi;
            unpack2(op[cc], lo, hi);
            sOut[tid][2 * cc]     = lo;
            sOut[tid][2 * cc + 1] = hi;
        }
    }
    __syncthreads();

    // segmented max over this block's edge range
    const int c = tid & 31;
    const int w = tid >> 5;
    const int nf = g_bstart[blockIdx.x];
    for (int n = nf + w; n < n_nodes; n += 8) {
        const int on  = g_offs[n];
        if (on >= e1) break;
        const int on1 = g_offs[n + 1];
        const int eb = max(on, e0);
        const int ee = min(on1, e1);
        float m = -INFINITY;
        for (int k = eb; k < ee; k++) m = fmaxf(m, sOut[k - e0][c]);
        const bool interior = (on >= e0) && (on1 <= e1);
        if (interior) {
            g_agg[(size_t)n * HID + c] = m;       // includes empty nodes: stores -inf, sanitized later
        } else if (eb < ee) {
            atomicMaxFloat(&g_agg[(size_t)n * HID + c], m);
        }
    }
}

// ---------------- kernel 9: BN stats (sanitize -inf on read) ----------------
__global__ void __launch_bounds__(256) stats_kernel(int n_nodes) {
    int t = threadIdx.x;
    float sum = 0.f, sq = 0.f;
    int total = n_nodes * HID;
    for (int i = blockIdx.x * blockDim.x + t; i < total; i += gridDim.x * blockDim.x) {
        float v = g_agg[i];
        if (!isfinite(v)) v = 0.f;
        sum += v;
        sq += v * v;
    }
    __shared__ float sS[256], sQ[256];
    sS[t] = sum; sQ[t] = sq;
    __syncthreads();
    #pragma unroll
    for (int s = 128; s >= 32; s >>= 1) {
        if (t < s) { sS[t] += sS[t + s]; sQ[t] += sQ[t + s]; }
        __syncthreads();
    }
    if (t < 32) {
        atomicAdd(&g_stats[t], sS[t]);
        atomicAdd(&g_stats[32 + t], sQ[t]);
    }
}

// ---------------- kernel 10: fold BN ----------------
__global__ void bn_kernel(const float* __restrict__ gamma, const float* __restrict__ beta,
                          int n_nodes) {
    int c = threadIdx.x;
    if (c >= HID) return;
    float inv_n = 1.f / (float)n_nodes;
    float mean = g_stats[c] * inv_n;
    float var = g_stats[HID + c] * inv_n - mean * mean;
    float sc = gamma[c] * rsqrtf(var + EPSV);
    g_scale[c] = sc;
    g_shift[c] = beta[c] - mean * sc;
}

// ---------------- kernel 11: normalize + relu + per-graph mean pool ----------------
__global__ void __launch_bounds__(256) pool_kernel(const int* __restrict__ batch,
                                                   int n_nodes) {
    int c = threadIdx.x & 31;
    int w = threadIdx.x >> 5;
    float sc = g_scale[c];
    float sh = g_shift[c];

    int chunk = (n_nodes + gridDim.x - 1) / gridDim.x;
    int n0 = blockIdx.x * chunk;
    int n1 = min(n0 + chunk, n_nodes);

    float acc = 0.f;
    int cur = -1;
    int cnt = 0;
    for (int n = n0 + w; n < n1; n += 8) {
        int g = batch[n];
        float v = g_agg[(size_t)n * HID + c];
        if (!isfinite(v)) v = 0.f;
        v = fmaxf(v * sc + sh, 0.f);
        if (g != cur) {
            if (cur >= 0) {
                atomicAdd(&g_gsum[cur * HID + c], acc);
                if (c == 0) atomicAdd(&g_gcnt[cur], cnt);
            }
            cur = g; acc = 0.f; cnt = 0;
        }
        acc += v; cnt++;
    }
    if (cur >= 0) {
        atomicAdd(&g_gsum[cur * HID + c], acc);
        if (c == 0) atomicAdd(&g_gcnt[cur], cnt);
    }
}

// ---------------- kernel 12: readout MLP ----------------
__global__ void final_kernel(const float* __restrict__ Wr1, const float* __restrict__ br1,
                             const float* __restrict__ Wr2, const float* __restrict__ br2,
                             float* __restrict__ out, int n_graphs) {
    int g = threadIdx.x + blockIdx.x * blockDim.x;
    if (g >= n_graphs) return;
    float inv_cnt = 1.f / fmaxf((float)g_gcnt[g], 1.f);
    float p[HID];
    #pragma unroll
    for (int c = 0; c < HID; c++) p[c] = g_gsum[g * HID + c] * inv_cnt;
    float h[16];
    #pragma unroll
    for (int m = 0; m < 16; m++) {
        float a = br1[m];
        #pragma unroll
        for (int c = 0; c < HID; c++) a += p[c] * Wr1[c * 16 + m];
        h[m] = fmaxf(a, 0.f);
    }
    float o = br2[0];
    #pragma unroll
    for (int m = 0; m < 16; m++) o += h[m] * Wr2[m];
    out[g] = o;
}

// ---------------- launch ----------------
extern "C" void kernel_launch(void* const* d_in, const int* in_sizes, int n_in,
                              void* d_out, int out_size) {
    const float* x     = (const float*)d_in[0];
    const int*   ei    = (const int*)d_in[1];
    const int*   batch = (const int*)d_in[2];
    const float* W1    = (const float*)d_in[3];
    const float* b1    = (const float*)d_in[4];
    const float* W2    = (const float*)d_in[5];
    const float* b2    = (const float*)d_in[6];
    const float* gamma = (const float*)d_in[7];
    const float* beta  = (const float*)d_in[8];
    const float* Wr1   = (const float*)d_in[9];
    const float* br1   = (const float*)d_in[10];
    const float* Wr2   = (const float*)d_in[11];
    const float* br2   = (const float*)d_in[12];
    float* out = (float*)d_out;

    int E        = in_sizes[1] / 2;
    int n_nodes  = in_sizes[2];
    int n_graphs = out_size;
    int eblocks  = (E + EB - 1) / EB;

    init_kernel<<<(n_nodes * HID + 255) / 256, 256>>>(n_nodes, n_graphs);
    hist_kernel<<<(E + 255) / 256, 256>>>(ei, E);
    scan_part_kernel<<<SCAN_BLOCKS, SCAN_BS>>>(n_nodes);
    scan_top_kernel<<<1, 512>>>();
    scan_add_kernel<<<SCAN_BLOCKS, SCAN_BS>>>(n_nodes, E);
    scatter_kernel<<<(E + 255) / 256, 256>>>(ei, E);
    bstart_kernel<<<(eblocks + 255) / 256, 256>>>(eblocks, n_nodes);
    edge2_kernel<<<eblocks, EB>>>(x, W1, b1, W2, b2, E, n_nodes);
    stats_kernel<<<592, 256>>>(n_nodes);
    bn_kernel<<<1, 32>>>(gamma, beta, n_nodes);
    pool_kernel<<<256, 256>>>(batch, n_nodes);
    final_kernel<<<1, 64>>>(Wr1, br1, Wr2, br2, out, n_graphs);
}